// round 17
// baseline (speedup 1.0000x reference)
#include <cuda_runtime.h>
#include <cuda_fp16.h>
#include <math.h>
#include <stdint.h>

// ---------------------------------------------------------------------------
// Attention_80642305950390 — round 17: PV mainloop accumulates its own row
// sums from A-fragments (P covers full K=2048 per CTA) -> rowsum kernel and
// g_inv eliminated. Scores GEMM stores exp(s) half (round 16).
// GEMM mainloop = round-11 config (BK=32, 4-stage, 128 thr, 64x64 warp tile).
//   B=4, S=2048, E=1024, A=1024.
// ---------------------------------------------------------------------------

#define Bq 4
#define Sq 2048
#define Eq 1024
#define Aq 1024
#define MS (Bq * Sq)

__device__ __half g_qh [(size_t)MS * Eq];
__device__ __half g_kh [(size_t)MS * Eq];
__device__ __half g_vh [(size_t)MS * Eq];
__device__ __half g_Wqt[(size_t)Eq * Aq];
__device__ __half g_Wkt[(size_t)Eq * Aq];
__device__ __half g_Wvt[(size_t)Eq * Aq];
__device__ __half g_Qh [(size_t)MS * Aq];
__device__ __half g_Kh [(size_t)MS * Aq];
__device__ __half g_Vth[(size_t)MS * Aq];      // per-batch V^T [b][A][S]
__device__ __half g_Ph [(size_t)Bq * Sq * Sq]; // unnormalized exp(scores), half

// ---------------------------------------------------------------------------
__device__ __forceinline__ uint32_t smem_u32(const void* p) {
    uint32_t a;
    asm("{ .reg .u64 t; cvta.to.shared.u64 t, %1; cvt.u32.u64 %0, t; }"
        : "=r"(a) : "l"(p));
    return a;
}
__device__ __forceinline__ void cp_async16(uint32_t smem, const void* gmem) {
    asm volatile("cp.async.cg.shared.global [%0], [%1], 16;\n" :: "r"(smem), "l"(gmem));
}
#define CP_COMMIT() asm volatile("cp.async.commit_group;\n" ::: "memory")
#define CP_WAIT(N)  asm volatile("cp.async.wait_group %0;\n" :: "n"(N) : "memory")

__device__ __forceinline__ void ldsm_x4(uint32_t addr, uint32_t* r) {
    asm volatile("ldmatrix.sync.aligned.m8n8.x4.shared.b16 {%0,%1,%2,%3}, [%4];"
                 : "=r"(r[0]), "=r"(r[1]), "=r"(r[2]), "=r"(r[3]) : "r"(addr));
}
__device__ __forceinline__ void mma_f16(float* d, const uint32_t* a,
                                        uint32_t b0, uint32_t b1) {
    asm volatile(
        "mma.sync.aligned.m16n8k16.row.col.f32.f16.f16.f32 "
        "{%0,%1,%2,%3},{%4,%5,%6,%7},{%8,%9},{%0,%1,%2,%3};"
        : "+f"(d[0]), "+f"(d[1]), "+f"(d[2]), "+f"(d[3])
        : "r"(a[0]), "r"(a[1]), "r"(a[2]), "r"(a[3]), "r"(b0), "r"(b1));
}

#define ROW_B 80
#define AB_PAD_BYTES (128 * ROW_B)
#define STAGE_BYTES (2 * AB_PAD_BYTES)
#define GEMM_SMEM (4 * STAGE_BYTES)           // 81920

// ---------------------------------------------------------------------------
// Shared mainloop: accumulates 128x128 tile of A[M,K] @ B[N,K]^T.
// 128 threads, 4 warps (2M x 2N), warp tile 64x64.
// ROWSUM: additionally accumulate fp32 row sums of A (half) fragments.
//   rowp[mi][0] -> row wm*64+mi*16+g ; rowp[mi][1] -> +8. Quad-partial
//   (complete after shfl_xor 1,2 across lanes t).
// ---------------------------------------------------------------------------
struct GemmCtx {
    float acc[4][8][4];
    float rowp[4][2];
};

template <bool ROWSUM>
__device__ __forceinline__ void gemm_mainloop(
    GemmCtx& ctx, const __half* __restrict__ A, const __half* __restrict__ B,
    int K, int cRow, int cCol, uint32_t smem_base,
    int tid, uint32_t a_lane, uint32_t b_lane)
{
    #pragma unroll
    for (int i = 0; i < 4; i++)
        #pragma unroll
        for (int j = 0; j < 8; j++)
            #pragma unroll
            for (int r = 0; r < 4; r++) ctx.acc[i][j][r] = 0.0f;
    if (ROWSUM) {
        #pragma unroll
        for (int i = 0; i < 4; i++) { ctx.rowp[i][0] = 0.0f; ctx.rowp[i][1] = 0.0f; }
    }

    const int NK = K >> 5;

    auto load_tile = [&](int stage, int kt) {
        const uint32_t As = smem_base + stage * STAGE_BYTES;
        const uint32_t Bs = As + AB_PAD_BYTES;
        const long long kbase = (long long)(kt << 5);
        #pragma unroll
        for (int i = 0; i < 4; i++) {
            const int ch  = tid + i * 128;
            const int row = ch >> 2;
            const int k4  = ch & 3;
            const uint32_t so = (uint32_t)(row * ROW_B + k4 * 16);
            cp_async16(As + so, &A[(long long)(cRow + row) * K + kbase + k4 * 8]);
            cp_async16(Bs + so, &B[(long long)(cCol + row) * K + kbase + k4 * 8]);
        }
    };

    load_tile(0, 0); CP_COMMIT();
    load_tile(1, 1); CP_COMMIT();
    load_tile(2, 2); CP_COMMIT();

    for (int kt = 0; kt < NK; kt++) {
        CP_WAIT(2);
        __syncthreads();

        if (kt + 3 < NK) load_tile((kt + 3) & 3, kt + 3);
        CP_COMMIT();

        const uint32_t sA_base = smem_base + (kt & 3) * STAGE_BYTES + a_lane;
        const uint32_t sB_base = smem_base + (kt & 3) * STAGE_BYTES + AB_PAD_BYTES + b_lane;

        uint32_t a[2][4][4], b[2][4][4];
        #pragma unroll
        for (int s = 0; s < 2; s++) {
            const uint32_t ko = s * 32;
            #pragma unroll
            for (int mi = 0; mi < 4; mi++)
                ldsm_x4(sA_base + mi * (16 * ROW_B) + ko, a[s][mi]);
            #pragma unroll
            for (int p = 0; p < 4; p++)
                ldsm_x4(sB_base + p * (16 * ROW_B) + ko, b[s][p]);
        }
        #pragma unroll
        for (int s = 0; s < 2; s++)
            #pragma unroll
            for (int p = 0; p < 4; p++)
                #pragma unroll
                for (int mi = 0; mi < 4; mi++) {
                    mma_f16(ctx.acc[mi][2 * p    ], a[s][mi], b[s][p][0], b[s][p][1]);
                    mma_f16(ctx.acc[mi][2 * p + 1], a[s][mi], b[s][p][2], b[s][p][3]);
                }

        if (ROWSUM) {
            #pragma unroll
            for (int s = 0; s < 2; s++)
                #pragma unroll
                for (int mi = 0; mi < 4; mi++) {
                    const float2 f0 = __half22float2(
                        *reinterpret_cast<const __half2*>(&a[s][mi][0]));
                    const float2 f2 = __half22float2(
                        *reinterpret_cast<const __half2*>(&a[s][mi][2]));
                    ctx.rowp[mi][0] += (f0.x + f0.y) + (f2.x + f2.y);
                    const float2 f1 = __half22float2(
                        *reinterpret_cast<const __half2*>(&a[s][mi][1]));
                    const float2 f3 = __half22float2(
                        *reinterpret_cast<const __half2*>(&a[s][mi][3]));
                    ctx.rowp[mi][1] += (f1.x + f1.y) + (f3.x + f3.y);
                }
        }
    }
}

// ---------------------------------------------------------------------------
// Merged QKV projection: grid (8, 64, 3). z: 0=Q, 1=K (half out), 2=V (half
// transposed out per batch [b][A][S]). M=8192, N=A=1024, K=E=1024, bias.
// ---------------------------------------------------------------------------
__global__ __launch_bounds__(128, 2)
void qkv_proj_kernel(const __half* __restrict__ qh, const __half* __restrict__ kh,
                     const __half* __restrict__ vh,
                     const __half* __restrict__ Wqt, const __half* __restrict__ Wkt,
                     const __half* __restrict__ Wvt,
                     const float* __restrict__ bq, const float* __restrict__ bk,
                     const float* __restrict__ bv,
                     __half* __restrict__ Qh, __half* __restrict__ Kh,
                     __half* __restrict__ Vth)
{
    extern __shared__ char smem[];
    const uint32_t smem_base = smem_u32(smem);
    const int z = blockIdx.z;

    const __half* A = (z == 0) ? qh : (z == 1) ? kh : vh;
    const __half* B = (z == 0) ? Wqt : (z == 1) ? Wkt : Wvt;
    const float* bias = (z == 0) ? bq : (z == 1) ? bk : bv;

    const int tid  = threadIdx.x;
    const int lane = tid & 31;
    const int wid  = tid >> 5;
    const int wm   = wid >> 1;
    const int wn   = wid & 1;
    const int g    = lane >> 2;
    const int t    = lane & 3;
    const int cRow = blockIdx.y * 128;
    const int cCol = blockIdx.x * 128;

    const uint32_t a_lane = (uint32_t)((wm * 64 + (lane & 15)) * ROW_B
                                       + (lane >> 4) * 16);
    const uint32_t b_lane = (uint32_t)((wn * 64 + (lane & 7) + ((lane >> 4) & 1) * 8) * ROW_B
                                       + ((lane >> 3) & 1) * 16);

    GemmCtx ctx;
    gemm_mainloop<false>(ctx, A, B, Eq, cRow, cCol, smem_base, tid, a_lane, b_lane);

    if (z != 2) {
        __half* C = (z == 0) ? Qh : Kh;
        #pragma unroll
        for (int mi = 0; mi < 4; mi++) {
            const int row0 = cRow + wm * 64 + mi * 16 + g;
            #pragma unroll
            for (int ni = 0; ni < 8; ni++) {
                const int col = cCol + wn * 64 + ni * 8 + t * 2;
                const float2 b2 = *reinterpret_cast<const float2*>(&bias[col]);
                *reinterpret_cast<__half2*>(&C[(long long)row0 * Aq + col]) =
                    __floats2half2_rn(ctx.acc[mi][ni][0] + b2.x,
                                      ctx.acc[mi][ni][1] + b2.y);
                *reinterpret_cast<__half2*>(&C[(long long)(row0 + 8) * Aq + col]) =
                    __floats2half2_rn(ctx.acc[mi][ni][2] + b2.x,
                                      ctx.acc[mi][ni][3] + b2.y);
            }
        }
    } else {
        // Transposed half store via smem staging [n_local][m_local].
        __syncthreads();
        __half* sT = reinterpret_cast<__half*>(smem);
        const int TP = 136;
        #pragma unroll
        for (int mi = 0; mi < 4; mi++) {
            const int ml0 = wm * 64 + mi * 16 + g;
            #pragma unroll
            for (int ni = 0; ni < 8; ni++) {
                const int nl = wn * 64 + ni * 8 + t * 2;
                const float2 b2 = *reinterpret_cast<const float2*>(&bias[cCol + nl]);
                sT[(nl    ) * TP + ml0    ] = __float2half_rn(ctx.acc[mi][ni][0] + b2.x);
                sT[(nl + 1) * TP + ml0    ] = __float2half_rn(ctx.acc[mi][ni][1] + b2.y);
                sT[(nl    ) * TP + ml0 + 8] = __float2half_rn(ctx.acc[mi][ni][2] + b2.x);
                sT[(nl + 1) * TP + ml0 + 8] = __float2half_rn(ctx.acc[mi][ni][3] + b2.y);
            }
        }
        __syncthreads();
        const int b    = cRow / Sq;
        const int mloc = cRow % Sq;
        #pragma unroll
        for (int i = 0; i < 16; i++) {
            const int idx = tid + i * 128;
            const int nl  = idx >> 4;
            const int m8  = (idx & 15) * 8;
            const long long co = ((long long)b * Aq + cCol + nl) * Sq + mloc + m8;
            float4 v = *reinterpret_cast<const float4*>(&sT[nl * TP + m8]);
            *reinterpret_cast<float4*>(&Vth[co]) = v;
        }
    }
}

// ---------------------------------------------------------------------------
// Attention GEMMs (NT).
//  MODE 1: scores -> store exp(alpha*acc) as half   (C = __half*)
//  MODE 2: PV -> fp32 out scaled by 1/rowsum (rowsum from A-fragments)
// ---------------------------------------------------------------------------
template <int MODE>
__global__ __launch_bounds__(128, 2)
void attn_gemm_kernel(const __half* __restrict__ A, const __half* __restrict__ B,
                      void* __restrict__ Cv,
                      int N, int K, float alpha,
                      long long sA, long long sB, long long sC)
{
    extern __shared__ char smem[];
    const uint32_t smem_base = smem_u32(smem);

    A += (long long)blockIdx.z * sA;
    B += (long long)blockIdx.z * sB;

    const int tid  = threadIdx.x;
    const int lane = tid & 31;
    const int wid  = tid >> 5;
    const int wm   = wid >> 1;
    const int wn   = wid & 1;
    const int g    = lane >> 2;
    const int t    = lane & 3;
    const int cRow = blockIdx.y * 128;
    const int cCol = blockIdx.x * 128;

    const uint32_t a_lane = (uint32_t)((wm * 64 + (lane & 15)) * ROW_B
                                       + (lane >> 4) * 16);
    const uint32_t b_lane = (uint32_t)((wn * 64 + (lane & 7) + ((lane >> 4) & 1) * 8) * ROW_B
                                       + ((lane >> 3) & 1) * 16);

    GemmCtx ctx;
    gemm_mainloop<MODE == 2>(ctx, A, B, K, cRow, cCol, smem_base, tid, a_lane, b_lane);

    if (MODE == 1) {
        __half* C = (__half*)Cv + (long long)blockIdx.z * sC;
        #pragma unroll
        for (int mi = 0; mi < 4; mi++) {
            const int row0 = cRow + wm * 64 + mi * 16 + g;
            #pragma unroll
            for (int ni = 0; ni < 8; ni++) {
                const int col = cCol + wn * 64 + ni * 8 + t * 2;
                *reinterpret_cast<__half2*>(&C[(long long)row0 * N + col]) =
                    __floats2half2_rn(__expf(ctx.acc[mi][ni][0] * alpha),
                                      __expf(ctx.acc[mi][ni][1] * alpha));
                *reinterpret_cast<__half2*>(&C[(long long)(row0 + 8) * N + col]) =
                    __floats2half2_rn(__expf(ctx.acc[mi][ni][2] * alpha),
                                      __expf(ctx.acc[mi][ni][3] * alpha));
            }
        }
    } else {
        // Complete row sums across the quad (lanes t = 0..3 tile k exactly).
        #pragma unroll
        for (int mi = 0; mi < 4; mi++)
            #pragma unroll
            for (int h = 0; h < 2; h++) {
                float v = ctx.rowp[mi][h];
                v += __shfl_xor_sync(0xffffffffu, v, 1);
                v += __shfl_xor_sync(0xffffffffu, v, 2);
                ctx.rowp[mi][h] = v;
            }

        float* C = (float*)Cv + (long long)blockIdx.z * sC;
        #pragma unroll
        for (int mi = 0; mi < 4; mi++) {
            const int row0 = cRow + wm * 64 + mi * 16 + g;
            const float i0 = 1.0f / ctx.rowp[mi][0];
            const float i1 = 1.0f / ctx.rowp[mi][1];
            #pragma unroll
            for (int ni = 0; ni < 8; ni++) {
                const int col = cCol + wn * 64 + ni * 8 + t * 2;
                float2 v0, v1;
                v0.x = ctx.acc[mi][ni][0] * i0;
                v0.y = ctx.acc[mi][ni][1] * i0;
                v1.x = ctx.acc[mi][ni][2] * i1;
                v1.y = ctx.acc[mi][ni][3] * i1;
                *reinterpret_cast<float2*>(&C[(long long)row0 * N + col]) = v0;
                *reinterpret_cast<float2*>(&C[(long long)(row0 + 8) * N + col]) = v1;
            }
        }
    }
}

// ---------------------------------------------------------------------------
__global__ __launch_bounds__(256)
void cvt3_kernel(const float* __restrict__ in0, const float* __restrict__ in1,
                 const float* __restrict__ in2,
                 __half2* __restrict__ o0, __half2* __restrict__ o1,
                 __half2* __restrict__ o2, int n4)
{
    const int z = blockIdx.z;
    const float* in = (z == 0) ? in0 : (z == 1) ? in1 : in2;
    __half2* out = (z == 0) ? o0 : (z == 1) ? o1 : o2;
    int i = blockIdx.x * blockDim.x + threadIdx.x;
    if (i < n4) {
        float4 v = reinterpret_cast<const float4*>(in)[i];
        out[2 * i    ] = __floats2half2_rn(v.x, v.y);
        out[2 * i + 1] = __floats2half2_rn(v.z, v.w);
    }
}

__global__ __launch_bounds__(256)
void transpose3_kernel(const float* __restrict__ w0, const float* __restrict__ w1,
                       const float* __restrict__ w2,
                       __half* __restrict__ o0, __half* __restrict__ o1,
                       __half* __restrict__ o2)
{
    const int z = blockIdx.z;
    const float* in = (z == 0) ? w0 : (z == 1) ? w1 : w2;
    __half* out = (z == 0) ? o0 : (z == 1) ? o1 : o2;
    __shared__ __half tbuf[32][33];
    const int tx = threadIdx.x, ty = threadIdx.y;
    const int a0 = blockIdx.x * 32;
    const int e0 = blockIdx.y * 32;
    #pragma unroll
    for (int r = 0; r < 4; r++)
        tbuf[ty + r * 8][tx] = __float2half_rn(
            in[(long long)(e0 + ty + r * 8) * Aq + a0 + tx]);
    __syncthreads();
    #pragma unroll
    for (int r = 0; r < 4; r++)
        out[(long long)(a0 + ty + r * 8) * Eq + e0 + tx] = tbuf[tx][ty + r * 8];
}

// ---------------------------------------------------------------------------
extern "C" void kernel_launch(void* const* d_in, const int* in_sizes, int n_in,
                              void* d_out, int out_size)
{
    const float* query = (const float*)d_in[0];
    const float* key   = (const float*)d_in[1];
    const float* value = (const float*)d_in[2];
    const float* Wq    = (const float*)d_in[3];
    const float* bq    = (const float*)d_in[4];
    const float* Wk    = (const float*)d_in[5];
    const float* bk    = (const float*)d_in[6];
    const float* Wv    = (const float*)d_in[7];
    const float* bv    = (const float*)d_in[8];
    float* out = (float*)d_out;

    __half *pqh, *pkh, *pvh, *pWqt, *pWkt, *pWvt, *pQh, *pKh, *pVth, *pPh;
    cudaGetSymbolAddress((void**)&pqh,  g_qh);
    cudaGetSymbolAddress((void**)&pkh,  g_kh);
    cudaGetSymbolAddress((void**)&pvh,  g_vh);
    cudaGetSymbolAddress((void**)&pWqt, g_Wqt);
    cudaGetSymbolAddress((void**)&pWkt, g_Wkt);
    cudaGetSymbolAddress((void**)&pWvt, g_Wvt);
    cudaGetSymbolAddress((void**)&pQh,  g_Qh);
    cudaGetSymbolAddress((void**)&pKh,  g_Kh);
    cudaGetSymbolAddress((void**)&pVth, g_Vth);
    cudaGetSymbolAddress((void**)&pPh,  g_Ph);

    static bool attr_done = false;
    if (!attr_done) {
        cudaFuncSetAttribute(qkv_proj_kernel,
            cudaFuncAttributeMaxDynamicSharedMemorySize, GEMM_SMEM);
        cudaFuncSetAttribute(attn_gemm_kernel<1>,
            cudaFuncAttributeMaxDynamicSharedMemorySize, GEMM_SMEM);
        cudaFuncSetAttribute(attn_gemm_kernel<2>,
            cudaFuncAttributeMaxDynamicSharedMemorySize, GEMM_SMEM);
        attr_done = true;
    }

    const int nin = MS * Eq / 4;

    // 1) input conversions (one grid, z=3)
    cvt3_kernel<<<dim3((nin + 255) / 256, 1, 3), 256>>>(
        query, key, value, (__half2*)pqh, (__half2*)pkh, (__half2*)pvh, nin);

    // 2) weight transposes (one grid, z=3)
    transpose3_kernel<<<dim3(Aq / 32, Eq / 32, 3), dim3(32, 8)>>>(
        Wq, Wk, Wv, pWqt, pWkt, pWvt);

    // 3) QKV projections (one grid, z=3; V^T fused)
    qkv_proj_kernel<<<dim3(Aq / 128, MS / 128, 3), 128, GEMM_SMEM>>>(
        pqh, pkh, pvh, pWqt, pWkt, pWvt, bq, bk, bv, pQh, pKh, pVth);

    // 4) exp(scores) = exp(Q @ K^T / 32) -> half, batched z=4
    attn_gemm_kernel<1><<<dim3(Sq / 128, Sq / 128, Bq), 128, GEMM_SMEM>>>(
        pQh, pKh, pPh, Sq, Aq, 1.0f / 32.0f,
        (long long)Sq * Aq, (long long)Sq * Aq, (long long)Sq * Sq);

    // 5) out = (expS @ (V^T)^T) / rowsum, batched z=4 -> d_out fp32
    //    (rowsum computed in-kernel from A-fragments)
    attn_gemm_kernel<2><<<dim3(Aq / 128, Sq / 128, Bq), 128, GEMM_SMEM>>>(
        pPh, pVth, out, Aq, Sq, 1.0f,
        (long long)Sq * Sq, (long long)Sq * Aq, (long long)Sq * Aq);
}